// round 14
// baseline (speedup 1.0000x reference)
#include <cuda_runtime.h>
#include <cstdint>

#define K_TOP    30
#define EMB_DIM  128
#define NT       128   // 4 warps per block; each block handles TWO graphs

// Map float -> uint32 whose unsigned order matches float order (ascending).
__device__ __forceinline__ unsigned int float_to_sortable(float f) {
    unsigned int b = __float_as_uint(f);
    return (b & 0x80000000u) ? ~b : (b | 0x80000000u);
}

__device__ __forceinline__ unsigned long long shflx64(unsigned long long x, int m) {
    unsigned lo = (unsigned)x, hi = (unsigned)(x >> 32);
    lo = __shfl_xor_sync(0xffffffffu, lo, m);
    hi = __shfl_xor_sync(0xffffffffu, hi, m);
    return ((unsigned long long)hi << 32) | lo;
}

__device__ __forceinline__ unsigned long long cmpx(unsigned long long a,
                                                   unsigned long long b,
                                                   bool keep_max) {
    unsigned long long mx = a > b ? a : b;
    unsigned long long mn = a > b ? b : a;
    return keep_max ? mx : mn;
}

// 5-stage descending bitonic merge (32-wide) of a bitonic sequence.
__device__ __forceinline__ unsigned long long warp_merge_desc(unsigned long long key,
                                                              int lane) {
    #pragma unroll
    for (int j = 16; j >= 1; j >>= 1) {
        bool lower = (lane & j) == 0;
        unsigned long long other = shflx64(key, j);
        key = cmpx(key, other, lower);
    }
    return key;
}

// Read-only (weak, L1-cached) vector load with a MEMORY CLOBBER: the clobber
// pins ordering against the surrounding C++ stores, so a sequence of these
// issues back-to-back (true MLP=8) BEFORE any store — while keeping cheap
// .nc load semantics instead of volatile's strong/L1-bypass path.
__device__ __forceinline__ float4 ldnc4(const float4* p) {
    float4 v;
    asm volatile("ld.global.nc.v4.f32 {%0,%1,%2,%3}, [%4];"
                 : "=f"(v.x), "=f"(v.y), "=f"(v.z), "=f"(v.w)
                 : "l"(p) : "memory");
    return v;
}

// 64-element descending bitonic sort, 2 keys per lane; returns warp top-32.
__device__ __forceinline__ unsigned long long warp_sort64_top32(
        unsigned long long key0, unsigned long long key1, int lane) {
    #pragma unroll
    for (int k = 2; k <= 16; k <<= 1) {
        const bool dir = ((lane & k) == 0);
        #pragma unroll
        for (int j = k >> 1; j >= 1; j >>= 1) {
            bool lower = (lane & j) == 0;
            key0 = cmpx(key0, shflx64(key0, j), lower == dir);
            key1 = cmpx(key1, shflx64(key1, j), lower == dir);
        }
    }
    // k = 32: key0 half descending, key1 half ascending.
    #pragma unroll
    for (int j = 16; j >= 1; j >>= 1) {
        bool lower = (lane & j) == 0;
        key0 = cmpx(key0, shflx64(key0, j), lower);
        key1 = cmpx(key1, shflx64(key1, j), !lower);
    }
    // k = 64: intra-thread compare keeps the top half, then 5-stage clean.
    unsigned long long mx = key0 > key1 ? key0 : key1;
    return warp_merge_desc(mx, lane);
}

__global__ void __launch_bounds__(NT)
sortpool_kernel(const float* __restrict__ emb,
                const int*   __restrict__ sizes,
                float*       __restrict__ out,
                int G) {
    const int gA   = 2 * blockIdx.x;
    const int gB   = gA + 1;
    const bool hasB = (gB < G);
    const int tid  = threadIdx.x;
    const int lane = tid & 31;
    const int wid  = tid >> 5;

    __shared__ unsigned long long s[NT];      // one 32-slot run per warp
    __shared__ int wsum[NT / 32];
    __shared__ int sh_off;
    __shared__ int topsA[32];
    __shared__ int topsB[32];

    // ---- offset of gA = prefix sum of sizes[0..gA-1] (done ONCE per CTA) ----
    int acc = 0;
    {
        const int4* s4 = (const int4*)sizes;
        const int nfull = gA >> 2;
        for (int j = tid; j < nfull; j += NT) {
            int4 v = s4[j];
            acc += v.x + v.y + v.z + v.w;
        }
        if (tid < (gA & 3)) acc += sizes[(nfull << 2) + tid];
    }
    #pragma unroll
    for (int m = 16; m; m >>= 1) acc += __shfl_xor_sync(0xffffffffu, acc, m);
    if (lane == 0) wsum[wid] = acc;
    __syncthreads();
    if (tid == 0) {
        int o = 0;
        #pragma unroll
        for (int w = 0; w < NT / 32; w++) o += wsum[w];
        sh_off = o;
    }
    __syncthreads();
    const int offA  = sh_off;
    const int sizeA = sizes[gA];
    const int offB  = offA + sizeA;
    const int sizeB = hasB ? sizes[gB] : 0;
    const int nwA   = (sizeA + 63) >> 6;
    const int nwB   = (sizeB + 63) >> 6;

    // ---- load keys for BOTH graphs up front (B's latency hides under phase A) ----
    // Composite key: (sortable(val) << 32) | ~elem_idx. Descending composite
    // order == descending value, ascending index on ties.
    const int i0 = (wid << 6) + lane;
    const int i1 = i0 + 32;
    unsigned long long a0 = (unsigned long long)(unsigned int)(~(unsigned int)i0);
    unsigned long long a1 = (unsigned long long)(unsigned int)(~(unsigned int)i1);
    unsigned long long b0 = a0, b1 = a1;

    if (wid < nwA && i0 < sizeA)
        a0 |= (unsigned long long)float_to_sortable(
                __ldg(&emb[(size_t)(offA + i0) * EMB_DIM + (EMB_DIM - 1)])) << 32;
    if (wid < nwA && i1 < sizeA)
        a1 |= (unsigned long long)float_to_sortable(
                __ldg(&emb[(size_t)(offA + i1) * EMB_DIM + (EMB_DIM - 1)])) << 32;
    if (wid < nwB && i0 < sizeB)
        b0 |= (unsigned long long)float_to_sortable(
                __ldg(&emb[(size_t)(offB + i0) * EMB_DIM + (EMB_DIM - 1)])) << 32;
    if (wid < nwB && i1 < sizeB)
        b1 |= (unsigned long long)float_to_sortable(
                __ldg(&emb[(size_t)(offB + i1) * EMB_DIM + (EMB_DIM - 1)])) << 32;

    // ================= PHASE A : sort + merge + gather graph gA =================
    unsigned long long keyA = 0;
    if (wid < nwA) {
        keyA = warp_sort64_top32(a0, a1, lane);
        s[(wid << 5) + lane] = keyA;
    }
    __syncthreads();
    for (int step = 1; step < nwA; step <<= 1) {
        bool winner = ((wid & (2 * step - 1)) == 0) && (wid + step < nwA);
        if (winner) {
            unsigned long long other = s[((wid + step) << 5) + (31 - lane)];
            keyA = keyA > other ? keyA : other;
            keyA = warp_merge_desc(keyA, lane);
            s[(wid << 5) + lane] = keyA;
        }
        __syncthreads();
    }
    const int kmaxA = min(K_TOP, sizeA);
    if (wid == 0) {
        int lidx = (int)(~(unsigned int)(keyA & 0xFFFFFFFFull));
        topsA[lane] = lidx;
        if (lane < K_TOP) {
            float idxval = (lane < kmaxA) ? (float)(offA + lidx) : -1.0f;
            out[(size_t)G * K_TOP * EMB_DIM + (size_t)gA * K_TOP + lane] = idxval;
        }
    }
    __syncthreads();

    {   // gather A: warp w owns rows {w, w+4, ..., w+28}, batched nc loads (MLP-8)
        float4*       out4 = (float4*)(out + (size_t)gA * K_TOP * EMB_DIM);
        const float4* emb4 = (const float4*)emb;
        const float4  zero = make_float4(0.f, 0.f, 0.f, 0.f);

        int addr[8];
        #pragma unroll
        for (int j = 0; j < 8; j++) {
            const int r = wid + 4 * j;
            addr[j] = (r < kmaxA) ? topsA[r] : topsA[0];
        }
        float4 v[8];
        #pragma unroll
        for (int j = 0; j < 8; j++)
            v[j] = ldnc4(&emb4[(size_t)(offA + addr[j]) * 32 + lane]);
        #pragma unroll
        for (int j = 0; j < 8; j++) {
            const int r = wid + 4 * j;
            if (r < K_TOP) out4[r * 32 + lane] = (r < kmaxA) ? v[j] : zero;
        }
    }

    // ================= PHASE B : sort overlaps A's store drain =================
    unsigned long long keyB = 0;
    if (wid < nwB) {
        keyB = warp_sort64_top32(b0, b1, lane);
        s[(wid << 5) + lane] = keyB;
    }
    __syncthreads();
    for (int step = 1; step < nwB; step <<= 1) {
        bool winner = ((wid & (2 * step - 1)) == 0) && (wid + step < nwB);
        if (winner) {
            unsigned long long other = s[((wid + step) << 5) + (31 - lane)];
            keyB = keyB > other ? keyB : other;
            keyB = warp_merge_desc(keyB, lane);
            s[(wid << 5) + lane] = keyB;
        }
        __syncthreads();
    }
    const int kmaxB = min(K_TOP, sizeB);
    if (hasB && wid == 0) {
        int lidx = (int)(~(unsigned int)(keyB & 0xFFFFFFFFull));
        topsB[lane] = lidx;
        if (lane < K_TOP) {
            float idxval = (lane < kmaxB) ? (float)(offB + lidx) : -1.0f;
            out[(size_t)G * K_TOP * EMB_DIM + (size_t)gB * K_TOP + lane] = idxval;
        }
    }
    __syncthreads();

    if (hasB) {   // gather B
        float4*       out4 = (float4*)(out + (size_t)gB * K_TOP * EMB_DIM);
        const float4* emb4 = (const float4*)emb;
        const float4  zero = make_float4(0.f, 0.f, 0.f, 0.f);

        int addr[8];
        #pragma unroll
        for (int j = 0; j < 8; j++) {
            const int r = wid + 4 * j;
            addr[j] = (r < kmaxB) ? topsB[r] : topsB[0];
        }
        float4 v[8];
        #pragma unroll
        for (int j = 0; j < 8; j++)
            v[j] = ldnc4(&emb4[(size_t)(offB + addr[j]) * 32 + lane]);
        #pragma unroll
        for (int j = 0; j < 8; j++) {
            const int r = wid + 4 * j;
            if (r < K_TOP) out4[r * 32 + lane] = (r < kmaxB) ? v[j] : zero;
        }
    }
}

extern "C" void kernel_launch(void* const* d_in, const int* in_sizes, int n_in,
                              void* d_out, int out_size) {
    const float* emb   = (const float*)d_in[0];
    const int*   sizes = (const int*)d_in[1];
    const int G = in_sizes[1];
    const int blocks = (G + 1) / 2;
    sortpool_kernel<<<blocks, NT>>>(emb, sizes, (float*)d_out, G);
}

// round 15
// speedup vs baseline: 1.1381x; 1.1381x over previous
#include <cuda_runtime.h>
#include <cstdint>

#define K_TOP    30
#define EMB_DIM  128
#define NT       128   // 4 warps per block; each block handles TWO graphs

// Map float -> uint32 whose unsigned order matches float order (ascending).
__device__ __forceinline__ unsigned int float_to_sortable(float f) {
    unsigned int b = __float_as_uint(f);
    return (b & 0x80000000u) ? ~b : (b | 0x80000000u);
}

__device__ __forceinline__ unsigned long long shflx64(unsigned long long x, int m) {
    unsigned lo = (unsigned)x, hi = (unsigned)(x >> 32);
    lo = __shfl_xor_sync(0xffffffffu, lo, m);
    hi = __shfl_xor_sync(0xffffffffu, hi, m);
    return ((unsigned long long)hi << 32) | lo;
}

__device__ __forceinline__ unsigned long long cmpx(unsigned long long a,
                                                   unsigned long long b,
                                                   bool keep_max) {
    unsigned long long mx = a > b ? a : b;
    unsigned long long mn = a > b ? b : a;
    return keep_max ? mx : mn;
}

// 5-stage descending bitonic merge (32-wide) of a bitonic sequence.
__device__ __forceinline__ unsigned long long warp_merge_desc(unsigned long long key,
                                                              int lane) {
    #pragma unroll
    for (int j = 16; j >= 1; j >>= 1) {
        bool lower = (lane & j) == 0;
        unsigned long long other = shflx64(key, j);
        key = cmpx(key, other, lower);
    }
    return key;
}

// Volatile vector load: lowers to a strong-class LDG that ptxas will NOT
// re-pair with the following stores, so a block of these issues back-to-back
// (true MLP=8) with results held in registers. This is the ONLY load form
// that survives ptxas's load/store re-pairing (verified R10 vs R13/R14).
__device__ __forceinline__ float4 ldv4(const float4* p) {
    float4 v;
    asm volatile("ld.volatile.global.v4.f32 {%0,%1,%2,%3}, [%4];"
                 : "=f"(v.x), "=f"(v.y), "=f"(v.z), "=f"(v.w)
                 : "l"(p) : "memory");
    return v;
}

// 64-element descending bitonic sort, 2 keys per lane; returns warp top-32.
__device__ __forceinline__ unsigned long long warp_sort64_top32(
        unsigned long long key0, unsigned long long key1, int lane) {
    #pragma unroll
    for (int k = 2; k <= 16; k <<= 1) {
        const bool dir = ((lane & k) == 0);
        #pragma unroll
        for (int j = k >> 1; j >= 1; j >>= 1) {
            bool lower = (lane & j) == 0;
            key0 = cmpx(key0, shflx64(key0, j), lower == dir);
            key1 = cmpx(key1, shflx64(key1, j), lower == dir);
        }
    }
    // k = 32: key0 half descending, key1 half ascending.
    #pragma unroll
    for (int j = 16; j >= 1; j >>= 1) {
        bool lower = (lane & j) == 0;
        key0 = cmpx(key0, shflx64(key0, j), lower);
        key1 = cmpx(key1, shflx64(key1, j), !lower);
    }
    // k = 64: intra-thread compare keeps the top half, then 5-stage clean.
    unsigned long long mx = key0 > key1 ? key0 : key1;
    return warp_merge_desc(mx, lane);
}

__global__ void __launch_bounds__(NT)
sortpool_kernel(const float* __restrict__ emb,
                const int*   __restrict__ sizes,
                float*       __restrict__ out,
                int G) {
    const int gA   = 2 * blockIdx.x;
    const int gB   = gA + 1;
    const bool hasB = (gB < G);
    const int tid  = threadIdx.x;
    const int lane = tid & 31;
    const int wid  = tid >> 5;

    __shared__ unsigned long long s[NT];      // one 32-slot run per warp
    __shared__ int wsum[NT / 32];
    __shared__ int sh_off;
    __shared__ int topsA[32];
    __shared__ int topsB[32];

    // ---- offset of gA = prefix sum of sizes[0..gA-1] (done ONCE per CTA) ----
    int acc = 0;
    {
        const int4* s4 = (const int4*)sizes;
        const int nfull = gA >> 2;
        for (int j = tid; j < nfull; j += NT) {
            int4 v = s4[j];
            acc += v.x + v.y + v.z + v.w;
        }
        if (tid < (gA & 3)) acc += sizes[(nfull << 2) + tid];
    }
    #pragma unroll
    for (int m = 16; m; m >>= 1) acc += __shfl_xor_sync(0xffffffffu, acc, m);
    if (lane == 0) wsum[wid] = acc;
    __syncthreads();
    if (tid == 0) {
        int o = 0;
        #pragma unroll
        for (int w = 0; w < NT / 32; w++) o += wsum[w];
        sh_off = o;
    }
    __syncthreads();
    const int offA  = sh_off;
    const int sizeA = sizes[gA];
    const int offB  = offA + sizeA;
    const int sizeB = hasB ? sizes[gB] : 0;
    const int nwA   = (sizeA + 63) >> 6;
    const int nwB   = (sizeB + 63) >> 6;

    // ---- load keys for BOTH graphs up front (B's latency hides under phase A) ----
    // Composite key: (sortable(val) << 32) | ~elem_idx. Descending composite
    // order == descending value, ascending index on ties.
    const int i0 = (wid << 6) + lane;
    const int i1 = i0 + 32;
    unsigned long long a0 = (unsigned long long)(unsigned int)(~(unsigned int)i0);
    unsigned long long a1 = (unsigned long long)(unsigned int)(~(unsigned int)i1);
    unsigned long long b0 = a0, b1 = a1;

    if (wid < nwA && i0 < sizeA)
        a0 |= (unsigned long long)float_to_sortable(
                __ldg(&emb[(size_t)(offA + i0) * EMB_DIM + (EMB_DIM - 1)])) << 32;
    if (wid < nwA && i1 < sizeA)
        a1 |= (unsigned long long)float_to_sortable(
                __ldg(&emb[(size_t)(offA + i1) * EMB_DIM + (EMB_DIM - 1)])) << 32;
    if (wid < nwB && i0 < sizeB)
        b0 |= (unsigned long long)float_to_sortable(
                __ldg(&emb[(size_t)(offB + i0) * EMB_DIM + (EMB_DIM - 1)])) << 32;
    if (wid < nwB && i1 < sizeB)
        b1 |= (unsigned long long)float_to_sortable(
                __ldg(&emb[(size_t)(offB + i1) * EMB_DIM + (EMB_DIM - 1)])) << 32;

    // ================= PHASE A : sort + merge + gather graph gA =================
    unsigned long long keyA = 0;
    if (wid < nwA) {
        keyA = warp_sort64_top32(a0, a1, lane);
        s[(wid << 5) + lane] = keyA;
    }
    __syncthreads();
    for (int step = 1; step < nwA; step <<= 1) {
        bool winner = ((wid & (2 * step - 1)) == 0) && (wid + step < nwA);
        if (winner) {
            unsigned long long other = s[((wid + step) << 5) + (31 - lane)];
            keyA = keyA > other ? keyA : other;
            keyA = warp_merge_desc(keyA, lane);
            s[(wid << 5) + lane] = keyA;
        }
        __syncthreads();
    }
    const int kmaxA = min(K_TOP, sizeA);
    if (wid == 0) {
        int lidx = (int)(~(unsigned int)(keyA & 0xFFFFFFFFull));
        topsA[lane] = lidx;
        if (lane < K_TOP) {
            float idxval = (lane < kmaxA) ? (float)(offA + lidx) : -1.0f;
            out[(size_t)G * K_TOP * EMB_DIM + (size_t)gA * K_TOP + lane] = idxval;
        }
    }
    __syncthreads();

    {   // gather A: warp w owns rows {w, w+4, ..., w+28}, volatile MLP-8
        float4*       out4 = (float4*)(out + (size_t)gA * K_TOP * EMB_DIM);
        const float4* emb4 = (const float4*)emb;
        const float4  zero = make_float4(0.f, 0.f, 0.f, 0.f);

        int addr[8];
        #pragma unroll
        for (int j = 0; j < 8; j++) {
            const int r = wid + 4 * j;
            addr[j] = (r < kmaxA) ? topsA[r] : topsA[0];
        }
        float4 v[8];
        #pragma unroll
        for (int j = 0; j < 8; j++)
            v[j] = ldv4(&emb4[(size_t)(offA + addr[j]) * 32 + lane]);
        #pragma unroll
        for (int j = 0; j < 8; j++) {
            const int r = wid + 4 * j;
            if (r < K_TOP) out4[r * 32 + lane] = (r < kmaxA) ? v[j] : zero;
        }
    }

    // ================= PHASE B : sort overlaps A's store drain =================
    unsigned long long keyB = 0;
    if (wid < nwB) {
        keyB = warp_sort64_top32(b0, b1, lane);
        s[(wid << 5) + lane] = keyB;
    }
    __syncthreads();
    for (int step = 1; step < nwB; step <<= 1) {
        bool winner = ((wid & (2 * step - 1)) == 0) && (wid + step < nwB);
        if (winner) {
            unsigned long long other = s[((wid + step) << 5) + (31 - lane)];
            keyB = keyB > other ? keyB : other;
            keyB = warp_merge_desc(keyB, lane);
            s[(wid << 5) + lane] = keyB;
        }
        __syncthreads();
    }
    const int kmaxB = min(K_TOP, sizeB);
    if (hasB && wid == 0) {
        int lidx = (int)(~(unsigned int)(keyB & 0xFFFFFFFFull));
        topsB[lane] = lidx;
        if (lane < K_TOP) {
            float idxval = (lane < kmaxB) ? (float)(offB + lidx) : -1.0f;
            out[(size_t)G * K_TOP * EMB_DIM + (size_t)gB * K_TOP + lane] = idxval;
        }
    }
    __syncthreads();

    if (hasB) {   // gather B
        float4*       out4 = (float4*)(out + (size_t)gB * K_TOP * EMB_DIM);
        const float4* emb4 = (const float4*)emb;
        const float4  zero = make_float4(0.f, 0.f, 0.f, 0.f);

        int addr[8];
        #pragma unroll
        for (int j = 0; j < 8; j++) {
            const int r = wid + 4 * j;
            addr[j] = (r < kmaxB) ? topsB[r] : topsB[0];
        }
        float4 v[8];
        #pragma unroll
        for (int j = 0; j < 8; j++)
            v[j] = ldv4(&emb4[(size_t)(offB + addr[j]) * 32 + lane]);
        #pragma unroll
        for (int j = 0; j < 8; j++) {
            const int r = wid + 4 * j;
            if (r < K_TOP) out4[r * 32 + lane] = (r < kmaxB) ? v[j] : zero;
        }
    }
}

extern "C" void kernel_launch(void* const* d_in, const int* in_sizes, int n_in,
                              void* d_out, int out_size) {
    const float* emb   = (const float*)d_in[0];
    const int*   sizes = (const int*)d_in[1];
    const int G = in_sizes[1];
    const int blocks = (G + 1) / 2;
    sortpool_kernel<<<blocks, NT>>>(emb, sizes, (float*)d_out, G);
}